// round 10
// baseline (speedup 1.0000x reference)
#include <cuda_runtime.h>
#include <cuda_fp16.h>
#include <math.h>

// Problem constants
#define BB   2
#define SS_  4096
#define DD   512
#define HH   8
#define DEP  64
#define BH   16
#define MM   8192

// Scratch: Q/K head-split [bh][s][d] fp16 (d pair-interleaved per 16);
// V TRANSPOSED [bh][d][s] fp16 (s pair-interleaved per 16).
__device__ __half g_qh[BH * SS_ * DEP];
__device__ __half g_kh[BH * SS_ * DEP];
__device__ __half g_vh[BH * SS_ * DEP];
__device__ float  g_ctx[MM * DD];
__device__ float  g_inv[BH * SS_];

__device__ __forceinline__ unsigned f2tf(float x) {
    unsigned u;
    asm("cvt.rna.tf32.f32 %0, %1;" : "=r"(u) : "f"(x));
    return u;
}

// Stored position of logical half j within a 16-chunk, such that a uint2 at
// word offset 2t yields halves (2t, 2t+1, 2t+8, 2t+9) = the fp16 mma fragment.
__device__ __forceinline__ int pos16(int j) {
    return 4 * ((j >> 1) & 3) + 2 * (j >> 3) + (j & 1);
}

__device__ __forceinline__ void mma_tf32(float* d, const unsigned* a, const unsigned* b) {
    asm volatile(
        "mma.sync.aligned.m16n8k8.row.col.f32.tf32.tf32.f32 "
        "{%0,%1,%2,%3}, {%4,%5,%6,%7}, {%8,%9}, {%0,%1,%2,%3};"
        : "+f"(d[0]), "+f"(d[1]), "+f"(d[2]), "+f"(d[3])
        : "r"(a[0]), "r"(a[1]), "r"(a[2]), "r"(a[3]), "r"(b[0]), "r"(b[1]));
}

__device__ __forceinline__ void mma_f16(float* d, const unsigned* a, const unsigned* b) {
    asm volatile(
        "mma.sync.aligned.m16n8k16.row.col.f32.f16.f16.f32 "
        "{%0,%1,%2,%3}, {%4,%5,%6,%7}, {%8,%9}, {%0,%1,%2,%3};"
        : "+f"(d[0]), "+f"(d[1]), "+f"(d[2]), "+f"(d[3])
        : "r"(a[0]), "r"(a[1]), "r"(a[2]), "r"(a[3]), "r"(b[0]), "r"(b[1]));
}

__device__ __forceinline__ void cp16(void* smem_ptr, const void* gptr) {
    unsigned s = (unsigned)__cvta_generic_to_shared(smem_ptr);
    asm volatile("cp.async.cg.shared.global [%0], [%1], 16;" :: "r"(s), "l"(gptr));
}
#define CP_COMMIT() asm volatile("cp.async.commit_group;" ::: "memory")
#define CP_WAIT0()  asm volatile("cp.async.wait_group 0;" ::: "memory")

// ---------------------------------------------------------------------------
// Projection GEMM: Y(8192x512) = X @ W + bias, tf32 MMA, cp.async pipelined.
// MODE 0: row-major fp32 out.
// MODE 1: head-split fp16, d pair-interleaved per 16 (Q, K).
// MODE 2: head-split TRANSPOSED [bh][d][s] fp16, s pair-interleaved (V).
// ---------------------------------------------------------------------------
template <int MODE>
__global__ void __launch_bounds__(256, 2)
gemm512_mma(const float* __restrict__ X, const float* __restrict__ W,
            const float* __restrict__ bias, float* __restrict__ Y) {
    extern __shared__ float psm[];
    float* Xb[2] = {psm, psm + 4608};            // [m][k] stride 36
    float* Wb[2] = {psm + 9216, psm + 13568};    // [k][n] stride 136

    const int tid = threadIdx.x;
    const int lane = tid & 31, w = tid >> 5;
    const int g = lane >> 2, t = lane & 3;
    const int wm = w & 3, wn = w >> 2;
    const int m0 = blockIdx.y * 128, n0 = blockIdx.x * 128;

    float acc[2][8][4];
#pragma unroll
    for (int mt = 0; mt < 2; mt++)
#pragma unroll
        for (int nt = 0; nt < 8; nt++)
#pragma unroll
            for (int c = 0; c < 4; c++) acc[mt][nt][c] = 0.f;

    const int xr = tid >> 1, xk = (tid & 1) * 16;
    const int wr = tid >> 3, wc = (tid & 7) * 16;

#pragma unroll
    for (int i = 0; i < 4; i++) {
        cp16(&Xb[0][xr * 36 + xk + i * 4], &X[(size_t)(m0 + xr) * 512 + xk + i * 4]);
        cp16(&Wb[0][wr * 136 + wc + i * 4], &W[(size_t)wr * 512 + n0 + wc + i * 4]);
    }
    CP_COMMIT();
    CP_WAIT0();
    __syncthreads();

    for (int it = 0; it < 16; it++) {
        if (it < 15) {
            const int k0 = (it + 1) * 32;
            float* Xn = Xb[(it + 1) & 1];
            float* Wn = Wb[(it + 1) & 1];
#pragma unroll
            for (int i = 0; i < 4; i++) {
                cp16(&Xn[xr * 36 + xk + i * 4], &X[(size_t)(m0 + xr) * 512 + k0 + xk + i * 4]);
                cp16(&Wn[wr * 136 + wc + i * 4], &W[(size_t)(k0 + wr) * 512 + n0 + wc + i * 4]);
            }
            CP_COMMIT();
        }
        const float* Xs = Xb[it & 1];
        const float* Ws = Wb[it & 1];
#pragma unroll
        for (int ks = 0; ks < 4; ks++) {
            const int kk = ks * 8;
            unsigned a[2][4];
#pragma unroll
            for (int mt = 0; mt < 2; mt++) {
                const int r0 = wm * 32 + mt * 16;
                a[mt][0] = f2tf(Xs[(r0 + g) * 36 + kk + t]);
                a[mt][1] = f2tf(Xs[(r0 + g + 8) * 36 + kk + t]);
                a[mt][2] = f2tf(Xs[(r0 + g) * 36 + kk + t + 4]);
                a[mt][3] = f2tf(Xs[(r0 + g + 8) * 36 + kk + t + 4]);
            }
#pragma unroll
            for (int nt = 0; nt < 8; nt++) {
                unsigned b[2];
                const int nn = wn * 64 + nt * 8 + g;
                b[0] = f2tf(Ws[(kk + t) * 136 + nn]);
                b[1] = f2tf(Ws[(kk + t + 4) * 136 + nn]);
                mma_tf32(acc[0][nt], a[0], b);
                mma_tf32(acc[1][nt], a[1], b);
            }
        }
        if (it < 15) {
            CP_WAIT0();
            __syncthreads();
        }
    }

    __half* Yh = (__half*)Y;
#pragma unroll
    for (int nt = 0; nt < 8; nt++) {
        const int colg = n0 + wn * 64 + nt * 8 + 2 * t;
        const float b0 = bias[colg], b1 = bias[colg + 1];
#pragma unroll
        for (int mt = 0; mt < 2; mt++) {
            const int rbase = m0 + wm * 32 + mt * 16;
#pragma unroll
            for (int half_ = 0; half_ < 2; half_++) {
                const int r = rbase + g + half_ * 8;
                float ox = acc[mt][nt][half_ * 2 + 0] + b0;
                float oy = acc[mt][nt][half_ * 2 + 1] + b1;
                if (MODE == 0) {
                    *(float2*)&Y[(size_t)r * 512 + colg] = make_float2(ox, oy);
                } else if (MODE == 1) {
                    const int b = r >> 12, s = r & 4095;
                    const int h = colg >> 6, din = colg & 63;
                    const int j16 = din & 15;  // even
                    const int pos = 4 * ((j16 >> 1) & 3) + 2 * (j16 >> 3);
                    __half2 o2 = __floats2half2_rn(ox, oy);
                    *(__half2*)&Yh[(((size_t)(b * 8 + h)) * SS_ + s) * DEP +
                                   (din & ~15) + pos] = o2;
                } else {
                    const int b = r >> 12, s = r & 4095;
                    const int sp = (s & ~15) | pos16(s & 15);
                    const int h = colg >> 6, d0 = colg & 63;
                    const size_t bh64 = (size_t)(b * 8 + h) * 64;
                    Yh[(bh64 + d0)     * SS_ + sp] = __float2half_rn(ox);
                    Yh[(bh64 + d0 + 1) * SS_ + sp] = __float2half_rn(oy);
                }
            }
        }
    }
}

// ---------------------------------------------------------------------------
// Causal flash attention, fp16 m16n8k16 MMA, cp.async double-buffered K/V.
// smem words: Qs/Ps [128][40]=5120, Kb[2][64*40]=5120, Vb[2][64*40]=5120
//   total 15360 words = 61440 B. Row = 64 halves (32 words) data, stride 40.
// ---------------------------------------------------------------------------
__global__ void __launch_bounds__(256, 2)
attn_kernel(float* __restrict__ attn_out, int write_attn) {
    extern __shared__ unsigned sm[];
    unsigned* Qs = sm;                              // reused as Ps
    unsigned* Kb[2] = {sm + 5120,  sm + 7680};
    unsigned* Vb[2] = {sm + 10240, sm + 12800};

    const int tid = threadIdx.x;
    const int lane = tid & 31, w = tid >> 5;
    const int g = lane >> 2, t = lane & 3;
    const int rt = 31 - blockIdx.x;     // heavy blocks first
    const int bh = blockIdx.y;
    const int row0 = rt * 128;

    const __half* __restrict__ Qh = g_qh + (size_t)bh * SS_ * DEP;
    const __half* __restrict__ Kh = g_kh + (size_t)bh * SS_ * DEP;
    const __half* __restrict__ Vh = g_vh + (size_t)bh * SS_ * DEP;  // [d][s]

    const int kvr = tid >> 2;                 // 0..63
    const int kvw = (tid & 3) * 8;            // smem word offset base

    // Prologue: Q (128x64h) + K0 + V0
    {
        const int qr = tid >> 1;
        const int qw = (tid & 1) * 16;        // word offset base
#pragma unroll
        for (int i = 0; i < 4; i++)
            cp16(&Qs[qr * 40 + qw + i * 4],
                 &Qh[(size_t)(row0 + qr) * DEP + 2 * (qw + i * 4)]);
    }
#pragma unroll
    for (int i = 0; i < 2; i++) {
        cp16(&Kb[0][kvr * 40 + kvw + i * 4], &Kh[(size_t)kvr * DEP + 2 * (kvw + i * 4)]);
        cp16(&Vb[0][kvr * 40 + kvw + i * 4], &Vh[(size_t)kvr * SS_ + 2 * (kvw + i * 4)]);
    }
    CP_COMMIT();
    CP_WAIT0();
    __syncthreads();

    // Q fragments: 4 ksteps (K=64), each {a0..a3} via two uint2 loads
    unsigned qa[4][4];
    {
        const int rq = w * 16;
#pragma unroll
        for (int ks = 0; ks < 4; ks++) {
            uint2 lo = *(const uint2*)&Qs[(rq + g) * 40 + ks * 8 + 2 * t];
            uint2 hi = *(const uint2*)&Qs[(rq + g + 8) * 40 + ks * 8 + 2 * t];
            qa[ks][0] = lo.x; qa[ks][1] = hi.x; qa[ks][2] = lo.y; qa[ks][3] = hi.y;
        }
    }

    float ctx[8][4];
#pragma unroll
    for (int nt = 0; nt < 8; nt++)
#pragma unroll
        for (int c = 0; c < 4; c++) ctx[nt][c] = 0.f;
    float rs0 = 0.f, rs1 = 0.f;

    const int gi0 = row0 + w * 16 + g;
    const int gi1 = gi0 + 8;
    const int ctmax = 2 * rt + 1;

    for (int ct = 0; ct <= ctmax; ct++) {
        if (ct < ctmax) {
            unsigned* Kn = Kb[(ct + 1) & 1];
            unsigned* Vn = Vb[(ct + 1) & 1];
            const size_t gk = (size_t)((ct + 1) * 64 + kvr) * DEP + 2 * kvw;
            const size_t gv = (size_t)kvr * SS_ + (ct + 1) * 64 + 2 * kvw;
#pragma unroll
            for (int i = 0; i < 2; i++) {
                cp16(&Kn[kvr * 40 + kvw + i * 4], &Kh[gk + i * 8]);
                cp16(&Vn[kvr * 40 + kvw + i * 4], &Vh[gv + i * 8]);
            }
            CP_COMMIT();
        }

        const unsigned* Ks = Kb[ct & 1];
        const unsigned* Vs = Vb[ct & 1];

        // GEMM1: S = Q K^T (warp 16x64), fp16 k16
        float s[8][4];
#pragma unroll
        for (int nt = 0; nt < 8; nt++)
#pragma unroll
            for (int c = 0; c < 4; c++) s[nt][c] = 0.f;
#pragma unroll
        for (int ks = 0; ks < 4; ks++) {
#pragma unroll
            for (int nt = 0; nt < 8; nt++) {
                uint2 bu = *(const uint2*)&Ks[(nt * 8 + g) * 40 + ks * 8 + 2 * t];
                unsigned b[2] = {bu.x, bu.y};
                mma_f16(s[nt], qa[ks], b);
            }
        }

        // exp + causal mask; fp32 P to gmem; fp16 P staged in Ps (=Qs)
        unsigned* Ps = Qs;
#pragma unroll
        for (int nt = 0; nt < 8; nt++) {
            const int cj = ct * 64 + nt * 8 + 2 * t;
            float e00 = (cj     <= gi0) ? __expf(s[nt][0] * 0.125f) : 0.f;
            float e01 = (cj + 1 <= gi0) ? __expf(s[nt][1] * 0.125f) : 0.f;
            float e10 = (cj     <= gi1) ? __expf(s[nt][2] * 0.125f) : 0.f;
            float e11 = (cj + 1 <= gi1) ? __expf(s[nt][3] * 0.125f) : 0.f;
            rs0 += e00 + e01;
            rs1 += e10 + e11;
            if (write_attn) {
                __stcs((float2*)&attn_out[((size_t)bh * SS_ + gi0) * SS_ + cj],
                       make_float2(e00, e01));
                __stcs((float2*)&attn_out[((size_t)bh * SS_ + gi1) * SS_ + cj],
                       make_float2(e10, e11));
            }
            // stored word = chunk*8 + 2t + (nt&1), chunk = nt>>1
            const int wo = (nt >> 1) * 8 + 2 * t + (nt & 1);
            *(__half2*)&Ps[(w * 16 + g) * 40 + wo]     = __floats2half2_rn(e00, e01);
            *(__half2*)&Ps[(w * 16 + g + 8) * 40 + wo] = __floats2half2_rn(e10, e11);
        }
        __syncwarp();

        // GEMM2: ctx += P V  (A = P frags from Ps, B = V^T frags)
#pragma unroll
        for (int ks = 0; ks < 4; ks++) {
            uint2 lo = *(const uint2*)&Ps[(w * 16 + g) * 40 + ks * 8 + 2 * t];
            uint2 hi = *(const uint2*)&Ps[(w * 16 + g + 8) * 40 + ks * 8 + 2 * t];
            unsigned pa[4] = {lo.x, hi.x, lo.y, hi.y};
#pragma unroll
            for (int nt = 0; nt < 8; nt++) {
                uint2 bu = *(const uint2*)&Vs[(nt * 8 + g) * 40 + ks * 8 + 2 * t];
                unsigned b[2] = {bu.x, bu.y};
                mma_f16(ctx[nt], pa, b);
            }
        }

        if (ct < ctmax) {
            CP_WAIT0();
            __syncthreads();
        }
    }

    // Row sums -> inv
    rs0 += __shfl_xor_sync(0xffffffffu, rs0, 1);
    rs0 += __shfl_xor_sync(0xffffffffu, rs0, 2);
    rs1 += __shfl_xor_sync(0xffffffffu, rs1, 1);
    rs1 += __shfl_xor_sync(0xffffffffu, rs1, 2);
    const float inv0 = 1.f / rs0, inv1 = 1.f / rs1;
    if (t == 0) {
        g_inv[(size_t)bh * SS_ + gi0] = inv0;
        g_inv[(size_t)bh * SS_ + gi1] = inv1;
    }

    // Store normalized ctx
    const int b = bh >> 3, h = bh & 7;
#pragma unroll
    for (int nt = 0; nt < 8; nt++) {
        const int d = nt * 8 + 2 * t;
        float2 o0, o1;
        o0.x = ctx[nt][0] * inv0; o0.y = ctx[nt][1] * inv0;
        o1.x = ctx[nt][2] * inv1; o1.y = ctx[nt][3] * inv1;
        *(float2*)&g_ctx[((size_t)(b * SS_ + gi0)) * DD + h * 64 + d] = o0;
        *(float2*)&g_ctx[((size_t)(b * SS_ + gi1)) * DD + h * 64 + d] = o1;
    }
}

// ---------------------------------------------------------------------------
// Normalize attn in place; zeros above diagonal (write-only there).
// ---------------------------------------------------------------------------
__global__ void __launch_bounds__(256)
normalize_attn(float* __restrict__ attn) {
    const size_t idx = (size_t)blockIdx.x * 256 + threadIdx.x;  // float4 index
    const int j4 = (int)(idx & 1023);
    const int i  = (int)((idx >> 10) & 4095);
    const int bh = (int)(idx >> 22);
    const int j  = j4 * 4;
    float4* p = (float4*)attn + idx;
    if (j > i) {
        __stcs(p, make_float4(0.f, 0.f, 0.f, 0.f));
    } else {
        const float inv = g_inv[(size_t)bh * SS_ + i];
        float4 v = __ldcs(p);
        if (j + 3 <= i) {
            v.x *= inv; v.y *= inv; v.z *= inv; v.w *= inv;
        } else {
            v.x = (j + 0 <= i) ? v.x * inv : 0.f;
            v.y = (j + 1 <= i) ? v.y * inv : 0.f;
            v.z = (j + 2 <= i) ? v.z * inv : 0.f;
            v.w = (j + 3 <= i) ? v.w * inv : 0.f;
        }
        __stcs(p, v);
    }
}

// ---------------------------------------------------------------------------
extern "C" void kernel_launch(void* const* d_in, const int* in_sizes, int n_in,
                              void* d_out, int out_size) {
    const float* q  = (const float*)d_in[2];
    const float* k  = (const float*)d_in[0];
    const float* v  = (const float*)d_in[1];
    const float* Wq = (const float*)d_in[4];
    const float* bq = (const float*)d_in[5];
    const float* Wk = (const float*)d_in[6];
    const float* bk = (const float*)d_in[7];
    const float* Wv = (const float*)d_in[8];
    const float* bv = (const float*)d_in[9];
    const float* Wo = (const float*)d_in[10];
    const float* bo = (const float*)d_in[11];

    float* out = (float*)d_out;
    const size_t BSD = (size_t)BB * SS_ * DD;
    const size_t ATT = (size_t)BH * SS_ * SS_;

    float* out_main = nullptr;
    float* attn_out = nullptr;
    if ((size_t)out_size >= BSD + ATT) {
        out_main = out;
        attn_out = out + BSD;
    } else if ((size_t)out_size >= ATT) {
        attn_out = out;
    } else {
        out_main = out;
    }

    void *pq, *pk, *pv, *pctx;
    cudaGetSymbolAddress(&pq, g_qh);
    cudaGetSymbolAddress(&pk, g_kh);
    cudaGetSymbolAddress(&pv, g_vh);
    cudaGetSymbolAddress(&pctx, g_ctx);

    cudaFuncSetAttribute(attn_kernel,
                         cudaFuncAttributeMaxDynamicSharedMemorySize, 61440);
    cudaFuncSetAttribute(gemm512_mma<0>,
                         cudaFuncAttributeMaxDynamicSharedMemorySize, 71680);
    cudaFuncSetAttribute(gemm512_mma<1>,
                         cudaFuncAttributeMaxDynamicSharedMemorySize, 71680);
    cudaFuncSetAttribute(gemm512_mma<2>,
                         cudaFuncAttributeMaxDynamicSharedMemorySize, 71680);

    dim3 ggrid(4, 64);
    gemm512_mma<1><<<ggrid, 256, 71680>>>(q, Wq, bq, (float*)pq);
    gemm512_mma<1><<<ggrid, 256, 71680>>>(k, Wk, bk, (float*)pk);
    gemm512_mma<2><<<ggrid, 256, 71680>>>(v, Wv, bv, (float*)pv);

    attn_kernel<<<dim3(32, BH), 256, 61440>>>(attn_out, attn_out != nullptr);

    if (attn_out) {
        normalize_attn<<<262144, 256>>>(attn_out);
    }
    if (out_main) {
        gemm512_mma<0><<<ggrid, 256, 71680>>>((const float*)pctx, Wo, bo, out_main);
    }
}

// round 11
// speedup vs baseline: 1.4759x; 1.4759x over previous
#include <cuda_runtime.h>
#include <cuda_fp16.h>
#include <math.h>

// Problem constants
#define BB   2
#define SS_  4096
#define DD   512
#define HH   8
#define DEP  64
#define BH   16
#define MM   8192

// Scratch: Q/K/V head-split [bh][s][d] fp16, natural layout.
__device__ __half g_qh[BH * SS_ * DEP];
__device__ __half g_kh[BH * SS_ * DEP];
__device__ __half g_vh[BH * SS_ * DEP];
__device__ float  g_ctx[MM * DD];
__device__ float  g_inv[BH * SS_];

__device__ __forceinline__ unsigned f2tf(float x) {
    unsigned u;
    asm("cvt.rna.tf32.f32 %0, %1;" : "=r"(u) : "f"(x));
    return u;
}

__device__ __forceinline__ float ex2(float x) {
    float y;
    asm("ex2.approx.ftz.f32 %0, %1;" : "=f"(y) : "f"(x));
    return y;
}

__device__ __forceinline__ void mma_tf32(float* d, const unsigned* a, const unsigned* b) {
    asm volatile(
        "mma.sync.aligned.m16n8k8.row.col.f32.tf32.tf32.f32 "
        "{%0,%1,%2,%3}, {%4,%5,%6,%7}, {%8,%9}, {%0,%1,%2,%3};"
        : "+f"(d[0]), "+f"(d[1]), "+f"(d[2]), "+f"(d[3])
        : "r"(a[0]), "r"(a[1]), "r"(a[2]), "r"(a[3]), "r"(b[0]), "r"(b[1]));
}

__device__ __forceinline__ void mma_f16(float* d, const unsigned* a, const unsigned* b) {
    asm volatile(
        "mma.sync.aligned.m16n8k16.row.col.f32.f16.f16.f32 "
        "{%0,%1,%2,%3}, {%4,%5,%6,%7}, {%8,%9}, {%0,%1,%2,%3};"
        : "+f"(d[0]), "+f"(d[1]), "+f"(d[2]), "+f"(d[3])
        : "r"(a[0]), "r"(a[1]), "r"(a[2]), "r"(a[3]), "r"(b[0]), "r"(b[1]));
}

__device__ __forceinline__ void ldsm4(unsigned* r, unsigned a) {
    asm volatile("ldmatrix.sync.aligned.m8n8.x4.shared.b16 {%0,%1,%2,%3}, [%4];"
                 : "=r"(r[0]), "=r"(r[1]), "=r"(r[2]), "=r"(r[3]) : "r"(a));
}
__device__ __forceinline__ void ldsm4t(unsigned* r, unsigned a) {
    asm volatile("ldmatrix.sync.aligned.m8n8.x4.trans.shared.b16 {%0,%1,%2,%3}, [%4];"
                 : "=r"(r[0]), "=r"(r[1]), "=r"(r[2]), "=r"(r[3]) : "r"(a));
}

__device__ __forceinline__ void cp16(void* smem_ptr, const void* gptr) {
    unsigned s = (unsigned)__cvta_generic_to_shared(smem_ptr);
    asm volatile("cp.async.cg.shared.global [%0], [%1], 16;" :: "r"(s), "l"(gptr));
}
#define CP_COMMIT() asm volatile("cp.async.commit_group;" ::: "memory")
#define CP_WAIT0()  asm volatile("cp.async.wait_group 0;" ::: "memory")
#define CP_WAIT1()  asm volatile("cp.async.wait_group 1;" ::: "memory")

// ---------------------------------------------------------------------------
// Projection GEMM: Y(8192x512) = X @ W + bias, tf32 MMA, cp.async pipelined.
// MODE 0: row-major fp32 out.
// MODE 1: head-split [bh][s][d] fp16 out (Q, K, V) — natural layout.
// ---------------------------------------------------------------------------
template <int MODE>
__global__ void __launch_bounds__(256, 2)
gemm512_mma(const float* __restrict__ X, const float* __restrict__ W,
            const float* __restrict__ bias, float* __restrict__ Y) {
    extern __shared__ float psm[];
    float* Xb[2] = {psm, psm + 4608};            // [m][k] stride 36
    float* Wb[2] = {psm + 9216, psm + 13568};    // [k][n] stride 136

    const int tid = threadIdx.x;
    const int lane = tid & 31, w = tid >> 5;
    const int g = lane >> 2, t = lane & 3;
    const int wm = w & 3, wn = w >> 2;
    const int m0 = blockIdx.y * 128, n0 = blockIdx.x * 128;

    float acc[2][8][4];
#pragma unroll
    for (int mt = 0; mt < 2; mt++)
#pragma unroll
        for (int nt = 0; nt < 8; nt++)
#pragma unroll
            for (int c = 0; c < 4; c++) acc[mt][nt][c] = 0.f;

    const int xr = tid >> 1, xk = (tid & 1) * 16;
    const int wr = tid >> 3, wc = (tid & 7) * 16;

#pragma unroll
    for (int i = 0; i < 4; i++) {
        cp16(&Xb[0][xr * 36 + xk + i * 4], &X[(size_t)(m0 + xr) * 512 + xk + i * 4]);
        cp16(&Wb[0][wr * 136 + wc + i * 4], &W[(size_t)wr * 512 + n0 + wc + i * 4]);
    }
    CP_COMMIT();
    CP_WAIT0();
    __syncthreads();

    for (int it = 0; it < 16; it++) {
        if (it < 15) {
            const int k0 = (it + 1) * 32;
            float* Xn = Xb[(it + 1) & 1];
            float* Wn = Wb[(it + 1) & 1];
#pragma unroll
            for (int i = 0; i < 4; i++) {
                cp16(&Xn[xr * 36 + xk + i * 4], &X[(size_t)(m0 + xr) * 512 + k0 + xk + i * 4]);
                cp16(&Wn[wr * 136 + wc + i * 4], &W[(size_t)(k0 + wr) * 512 + n0 + wc + i * 4]);
            }
            CP_COMMIT();
        }
        const float* Xs = Xb[it & 1];
        const float* Ws = Wb[it & 1];
#pragma unroll
        for (int ks = 0; ks < 4; ks++) {
            const int kk = ks * 8;
            unsigned a[2][4];
#pragma unroll
            for (int mt = 0; mt < 2; mt++) {
                const int r0 = wm * 32 + mt * 16;
                a[mt][0] = f2tf(Xs[(r0 + g) * 36 + kk + t]);
                a[mt][1] = f2tf(Xs[(r0 + g + 8) * 36 + kk + t]);
                a[mt][2] = f2tf(Xs[(r0 + g) * 36 + kk + t + 4]);
                a[mt][3] = f2tf(Xs[(r0 + g + 8) * 36 + kk + t + 4]);
            }
#pragma unroll
            for (int nt = 0; nt < 8; nt++) {
                unsigned b[2];
                const int nn = wn * 64 + nt * 8 + g;
                b[0] = f2tf(Ws[(kk + t) * 136 + nn]);
                b[1] = f2tf(Ws[(kk + t + 4) * 136 + nn]);
                mma_tf32(acc[0][nt], a[0], b);
                mma_tf32(acc[1][nt], a[1], b);
            }
        }
        if (it < 15) {
            CP_WAIT0();
            __syncthreads();
        }
    }

    __half* Yh = (__half*)Y;
#pragma unroll
    for (int nt = 0; nt < 8; nt++) {
        const int colg = n0 + wn * 64 + nt * 8 + 2 * t;
        const float b0 = bias[colg], b1 = bias[colg + 1];
#pragma unroll
        for (int mt = 0; mt < 2; mt++) {
            const int rbase = m0 + wm * 32 + mt * 16;
#pragma unroll
            for (int half_ = 0; half_ < 2; half_++) {
                const int r = rbase + g + half_ * 8;
                float ox = acc[mt][nt][half_ * 2 + 0] + b0;
                float oy = acc[mt][nt][half_ * 2 + 1] + b1;
                if (MODE == 0) {
                    *(float2*)&Y[(size_t)r * 512 + colg] = make_float2(ox, oy);
                } else {
                    const int b = r >> 12, s = r & 4095;
                    const int h = colg >> 6, din = colg & 63;
                    *(__half2*)&Yh[(((size_t)(b * 8 + h)) * SS_ + s) * DEP + din] =
                        __floats2half2_rn(ox, oy);
                }
            }
        }
    }
}

// ---------------------------------------------------------------------------
// Causal flash attention, fp16 m16n8k16 MMA, ldmatrix fragments,
// 3-stage cp.async K/V pipeline.
// smem halves: Qs[128*72]=9216 (reused as Ps), Kst[3][64*72], Vst[3][64*72]
//   total 36864 halves = 73728 B.
// ---------------------------------------------------------------------------
__global__ void __launch_bounds__(256, 2)
attn_kernel(float* __restrict__ attn_out, int write_attn) {
    extern __shared__ __half smh[];
    __half* Qs = smh;

    const int tid = threadIdx.x;
    const int lane = tid & 31, w = tid >> 5;
    const int g = lane >> 2, t = lane & 3;
    const int rt = 31 - blockIdx.x;     // heavy blocks first
    const int bh = blockIdx.y;
    const int row0 = rt * 128;

    const __half* __restrict__ Qh = g_qh + (size_t)bh * SS_ * DEP;
    const __half* __restrict__ Kh = g_kh + (size_t)bh * SS_ * DEP;
    const __half* __restrict__ Vh = g_vh + (size_t)bh * SS_ * DEP;

    const unsigned sbase = (unsigned)__cvta_generic_to_shared(smh);
    const unsigned kbase = sbase + 9216 * 2;      // Kst[0]
    const unsigned vbase = sbase + 23040 * 2;     // Vst[0]

    // ldmatrix per-lane offsets (bytes)
    const unsigned offA = (((lane & 15) * 72 + (lane >> 4) * 8) * 2);
    const unsigned offK = ((((lane >> 4) * 8 + (lane & 7)) * 72 + ((lane >> 3) & 1) * 8) * 2);
    const unsigned qpA = sbase + (w * 16 * 72) * 2 + offA;

    // cp.async mappings
    const int kvr = tid >> 2;            // 0..63
    const int c4 = tid & 3;

    // Prologue group 0: Q + K0 + V0
    {
        const int qr = tid >> 1;
        const int qo = (tid & 1) * 32;
#pragma unroll
        for (int i = 0; i < 4; i++)
            cp16(&Qs[qr * 72 + qo + i * 8], &Qh[(size_t)(row0 + qr) * DEP + qo + i * 8]);
    }
    __half* K0 = smh + 9216;
    __half* V0 = smh + 23040;
#pragma unroll
    for (int i = 0; i < 2; i++) {
        const int ho = 8 * c4 + 32 * i;
        cp16(&K0[kvr * 72 + ho], &Kh[(size_t)kvr * DEP + ho]);
        cp16(&V0[kvr * 72 + ho], &Vh[(size_t)kvr * DEP + ho]);
    }
    CP_COMMIT();
    // Prologue group 1: K1 + V1 (ctmax >= 1 always)
    {
        __half* K1 = smh + 9216 + 4608;
        __half* V1 = smh + 23040 + 4608;
#pragma unroll
        for (int i = 0; i < 2; i++) {
            const int ho = 8 * c4 + 32 * i;
            cp16(&K1[kvr * 72 + ho], &Kh[(size_t)(64 + kvr) * DEP + ho]);
            cp16(&V1[kvr * 72 + ho], &Vh[(size_t)(64 + kvr) * DEP + ho]);
        }
        CP_COMMIT();
    }
    CP_WAIT1();
    __syncthreads();

    // Q fragments (warp's own 16 rows): 4 ksteps via ldmatrix.x4
    unsigned qa[4][4];
#pragma unroll
    for (int ks = 0; ks < 4; ks++) ldsm4(qa[ks], qpA + ks * 32);

    float ctx[8][4];
#pragma unroll
    for (int nt = 0; nt < 8; nt++)
#pragma unroll
        for (int c = 0; c < 4; c++) ctx[nt][c] = 0.f;
    float rs0 = 0.f, rs1 = 0.f;

    const int gi0 = row0 + w * 16 + g;
    const int gi1 = gi0 + 8;
    const int ctmax = 2 * rt + 1;
    const float C = 0.18033688f;  // 0.125 * log2(e)

    for (int ct = 0; ct <= ctmax; ct++) {
        if (ct + 2 <= ctmax) {
            const int st = (ct + 2) % 3;
            __half* Kn = smh + 9216 + st * 4608;
            __half* Vn = smh + 23040 + st * 4608;
            const size_t gr = (size_t)((ct + 2) * 64 + kvr) * DEP;
#pragma unroll
            for (int i = 0; i < 2; i++) {
                const int ho = 8 * c4 + 32 * i;
                cp16(&Kn[kvr * 72 + ho], &Kh[gr + ho]);
                cp16(&Vn[kvr * 72 + ho], &Vh[gr + ho]);
            }
            CP_COMMIT();
        }

        const int st = ct % 3;
        const unsigned Kb = kbase + st * 4608 * 2;
        const unsigned Vb = vbase + st * 4608 * 2;

        // GEMM1: S = Q K^T (warp 16x64)
        float s[8][4];
#pragma unroll
        for (int nt = 0; nt < 8; nt++)
#pragma unroll
            for (int c = 0; c < 4; c++) s[nt][c] = 0.f;
#pragma unroll
        for (int ks = 0; ks < 4; ks++) {
#pragma unroll
            for (int ntp = 0; ntp < 4; ntp++) {
                unsigned bk[4];
                ldsm4(bk, Kb + ntp * 2304 + ks * 32 + offK);
                mma_f16(s[2 * ntp],     qa[ks], bk);
                mma_f16(s[2 * ntp + 1], qa[ks], bk + 2);
            }
        }

        // exp + causal mask; fp32 P to gmem; fp16 P staged in Ps (=Qs, own rows)
#pragma unroll
        for (int nt = 0; nt < 8; nt++) {
            const int cj = ct * 64 + nt * 8 + 2 * t;
            float e00 = (cj     <= gi0) ? ex2(s[nt][0] * C) : 0.f;
            float e01 = (cj + 1 <= gi0) ? ex2(s[nt][1] * C) : 0.f;
            float e10 = (cj     <= gi1) ? ex2(s[nt][2] * C) : 0.f;
            float e11 = (cj + 1 <= gi1) ? ex2(s[nt][3] * C) : 0.f;
            rs0 += e00 + e01;
            rs1 += e10 + e11;
            if (write_attn) {
                __stcs((float2*)&attn_out[((size_t)bh * SS_ + gi0) * SS_ + cj],
                       make_float2(e00, e01));
                __stcs((float2*)&attn_out[((size_t)bh * SS_ + gi1) * SS_ + cj],
                       make_float2(e10, e11));
            }
            *(__half2*)&Qs[(w * 16 + g) * 72 + nt * 8 + 2 * t]     = __floats2half2_rn(e00, e01);
            *(__half2*)&Qs[(w * 16 + g + 8) * 72 + nt * 8 + 2 * t] = __floats2half2_rn(e10, e11);
        }
        __syncwarp();

        // GEMM2: ctx += P V ; V fragments via ldmatrix.trans on [s][d]
#pragma unroll
        for (int ks = 0; ks < 4; ks++) {
            unsigned pa[4];
            ldsm4(pa, qpA + ks * 32);
#pragma unroll
            for (int ntp = 0; ntp < 4; ntp++) {
                unsigned bv[4];
                ldsm4t(bv, Vb + ks * 2304 + ntp * 32 + offA);
                mma_f16(ctx[2 * ntp],     pa, bv);
                mma_f16(ctx[2 * ntp + 1], pa, bv + 2);
            }
        }

        if (ct < ctmax) {
            if (ct + 2 <= ctmax) { CP_WAIT1(); } else { CP_WAIT0(); }
            __syncthreads();
        }
    }

    // Row sums -> inv
    rs0 += __shfl_xor_sync(0xffffffffu, rs0, 1);
    rs0 += __shfl_xor_sync(0xffffffffu, rs0, 2);
    rs1 += __shfl_xor_sync(0xffffffffu, rs1, 1);
    rs1 += __shfl_xor_sync(0xffffffffu, rs1, 2);
    const float inv0 = 1.f / rs0, inv1 = 1.f / rs1;
    if (t == 0) {
        g_inv[(size_t)bh * SS_ + gi0] = inv0;
        g_inv[(size_t)bh * SS_ + gi1] = inv1;
    }

    // Store normalized ctx
    const int b = bh >> 3, h = bh & 7;
#pragma unroll
    for (int nt = 0; nt < 8; nt++) {
        const int d = nt * 8 + 2 * t;
        float2 o0, o1;
        o0.x = ctx[nt][0] * inv0; o0.y = ctx[nt][1] * inv0;
        o1.x = ctx[nt][2] * inv1; o1.y = ctx[nt][3] * inv1;
        *(float2*)&g_ctx[((size_t)(b * SS_ + gi0)) * DD + h * 64 + d] = o0;
        *(float2*)&g_ctx[((size_t)(b * SS_ + gi1)) * DD + h * 64 + d] = o1;
    }
}

// ---------------------------------------------------------------------------
// Normalize attn in place; zeros above diagonal (write-only there).
// ---------------------------------------------------------------------------
__global__ void __launch_bounds__(256)
normalize_attn(float* __restrict__ attn) {
    const size_t idx = (size_t)blockIdx.x * 256 + threadIdx.x;  // float4 index
    const int j4 = (int)(idx & 1023);
    const int i  = (int)((idx >> 10) & 4095);
    const int bh = (int)(idx >> 22);
    const int j  = j4 * 4;
    float4* p = (float4*)attn + idx;
    if (j > i) {
        __stcs(p, make_float4(0.f, 0.f, 0.f, 0.f));
    } else {
        const float inv = g_inv[(size_t)bh * SS_ + i];
        float4 v = __ldcs(p);
        if (j + 3 <= i) {
            v.x *= inv; v.y *= inv; v.z *= inv; v.w *= inv;
        } else {
            v.x = (j + 0 <= i) ? v.x * inv : 0.f;
            v.y = (j + 1 <= i) ? v.y * inv : 0.f;
            v.z = (j + 2 <= i) ? v.z * inv : 0.f;
            v.w = (j + 3 <= i) ? v.w * inv : 0.f;
        }
        __stcs(p, v);
    }
}

// ---------------------------------------------------------------------------
extern "C" void kernel_launch(void* const* d_in, const int* in_sizes, int n_in,
                              void* d_out, int out_size) {
    const float* q  = (const float*)d_in[2];
    const float* k  = (const float*)d_in[0];
    const float* v  = (const float*)d_in[1];
    const float* Wq = (const float*)d_in[4];
    const float* bq = (const float*)d_in[5];
    const float* Wk = (const float*)d_in[6];
    const float* bk = (const float*)d_in[7];
    const float* Wv = (const float*)d_in[8];
    const float* bv = (const float*)d_in[9];
    const float* Wo = (const float*)d_in[10];
    const float* bo = (const float*)d_in[11];

    float* out = (float*)d_out;
    const size_t BSD = (size_t)BB * SS_ * DD;
    const size_t ATT = (size_t)BH * SS_ * SS_;

    float* out_main = nullptr;
    float* attn_out = nullptr;
    if ((size_t)out_size >= BSD + ATT) {
        out_main = out;
        attn_out = out + BSD;
    } else if ((size_t)out_size >= ATT) {
        attn_out = out;
    } else {
        out_main = out;
    }

    void *pq, *pk, *pv, *pctx;
    cudaGetSymbolAddress(&pq, g_qh);
    cudaGetSymbolAddress(&pk, g_kh);
    cudaGetSymbolAddress(&pv, g_vh);
    cudaGetSymbolAddress(&pctx, g_ctx);

    cudaFuncSetAttribute(attn_kernel,
                         cudaFuncAttributeMaxDynamicSharedMemorySize, 73728);
    cudaFuncSetAttribute(gemm512_mma<0>,
                         cudaFuncAttributeMaxDynamicSharedMemorySize, 71680);
    cudaFuncSetAttribute(gemm512_mma<1>,
                         cudaFuncAttributeMaxDynamicSharedMemorySize, 71680);

    dim3 ggrid(4, 64);
    gemm512_mma<1><<<ggrid, 256, 71680>>>(q, Wq, bq, (float*)pq);
    gemm512_mma<1><<<ggrid, 256, 71680>>>(k, Wk, bk, (float*)pk);
    gemm512_mma<1><<<ggrid, 256, 71680>>>(v, Wv, bv, (float*)pv);

    attn_kernel<<<dim3(32, BH), 256, 73728>>>(attn_out, attn_out != nullptr);

    if (attn_out) {
        normalize_attn<<<262144, 256>>>(attn_out);
    }
    if (out_main) {
        gemm512_mma<0><<<ggrid, 256, 71680>>>((const float*)pctx, Wo, bo, out_main);
    }
}

// round 12
// speedup vs baseline: 1.7056x; 1.1556x over previous
#include <cuda_runtime.h>
#include <cuda_fp16.h>
#include <math.h>

// Problem constants
#define BB   2
#define SS_  4096
#define DD   512
#define HH   8
#define DEP  64
#define BH   16
#define MM   8192

// Scratch: Q/K/V head-split [bh][s][d] fp16, natural layout.
__device__ __half g_qh[BH * SS_ * DEP];
__device__ __half g_kh[BH * SS_ * DEP];
__device__ __half g_vh[BH * SS_ * DEP];
__device__ float  g_ctx[MM * DD];
__device__ float  g_inv[BH * SS_];

__device__ __forceinline__ unsigned f2tf(float x) {
    unsigned u;
    asm("cvt.rna.tf32.f32 %0, %1;" : "=r"(u) : "f"(x));
    return u;
}

__device__ __forceinline__ float ex2(float x) {
    float y;
    asm("ex2.approx.ftz.f32 %0, %1;" : "=f"(y) : "f"(x));
    return y;
}

__device__ __forceinline__ void mma_tf32(float* d, const unsigned* a, const unsigned* b) {
    asm volatile(
        "mma.sync.aligned.m16n8k8.row.col.f32.tf32.tf32.f32 "
        "{%0,%1,%2,%3}, {%4,%5,%6,%7}, {%8,%9}, {%0,%1,%2,%3};"
        : "+f"(d[0]), "+f"(d[1]), "+f"(d[2]), "+f"(d[3])
        : "r"(a[0]), "r"(a[1]), "r"(a[2]), "r"(a[3]), "r"(b[0]), "r"(b[1]));
}

__device__ __forceinline__ void mma_f16(float* d, const unsigned* a, const unsigned* b) {
    asm volatile(
        "mma.sync.aligned.m16n8k16.row.col.f32.f16.f16.f32 "
        "{%0,%1,%2,%3}, {%4,%5,%6,%7}, {%8,%9}, {%0,%1,%2,%3};"
        : "+f"(d[0]), "+f"(d[1]), "+f"(d[2]), "+f"(d[3])
        : "r"(a[0]), "r"(a[1]), "r"(a[2]), "r"(a[3]), "r"(b[0]), "r"(b[1]));
}

__device__ __forceinline__ void ldsm4(unsigned* r, unsigned a) {
    asm volatile("ldmatrix.sync.aligned.m8n8.x4.shared.b16 {%0,%1,%2,%3}, [%4];"
                 : "=r"(r[0]), "=r"(r[1]), "=r"(r[2]), "=r"(r[3]) : "r"(a));
}
__device__ __forceinline__ void ldsm4t(unsigned* r, unsigned a) {
    asm volatile("ldmatrix.sync.aligned.m8n8.x4.trans.shared.b16 {%0,%1,%2,%3}, [%4];"
                 : "=r"(r[0]), "=r"(r[1]), "=r"(r[2]), "=r"(r[3]) : "r"(a));
}

__device__ __forceinline__ void cp16(void* smem_ptr, const void* gptr) {
    unsigned s = (unsigned)__cvta_generic_to_shared(smem_ptr);
    asm volatile("cp.async.cg.shared.global [%0], [%1], 16;" :: "r"(s), "l"(gptr));
}
#define CP_COMMIT() asm volatile("cp.async.commit_group;" ::: "memory")
#define CP_WAIT0()  asm volatile("cp.async.wait_group 0;" ::: "memory")
#define CP_WAIT1()  asm volatile("cp.async.wait_group 1;" ::: "memory")

// ---------------------------------------------------------------------------
// Projection GEMM: Y(8192x512) = X @ W + bias, tf32 MMA, cp.async pipelined.
// MODE 0: row-major fp32 out.
// MODE 1: head-split [bh][s][d] fp16 out (Q, K, V) — natural layout.
// ---------------------------------------------------------------------------
template <int MODE>
__global__ void __launch_bounds__(256, 2)
gemm512_mma(const float* __restrict__ X, const float* __restrict__ W,
            const float* __restrict__ bias, float* __restrict__ Y) {
    extern __shared__ float psm[];
    float* Xb[2] = {psm, psm + 4608};            // [m][k] stride 36
    float* Wb[2] = {psm + 9216, psm + 13568};    // [k][n] stride 136

    const int tid = threadIdx.x;
    const int lane = tid & 31, w = tid >> 5;
    const int g = lane >> 2, t = lane & 3;
    const int wm = w & 3, wn = w >> 2;
    const int m0 = blockIdx.y * 128, n0 = blockIdx.x * 128;

    float acc[2][8][4];
#pragma unroll
    for (int mt = 0; mt < 2; mt++)
#pragma unroll
        for (int nt = 0; nt < 8; nt++)
#pragma unroll
            for (int c = 0; c < 4; c++) acc[mt][nt][c] = 0.f;

    const int xr = tid >> 1, xk = (tid & 1) * 16;
    const int wr = tid >> 3, wc = (tid & 7) * 16;

#pragma unroll
    for (int i = 0; i < 4; i++) {
        cp16(&Xb[0][xr * 36 + xk + i * 4], &X[(size_t)(m0 + xr) * 512 + xk + i * 4]);
        cp16(&Wb[0][wr * 136 + wc + i * 4], &W[(size_t)wr * 512 + n0 + wc + i * 4]);
    }
    CP_COMMIT();
    CP_WAIT0();
    __syncthreads();

    for (int it = 0; it < 16; it++) {
        if (it < 15) {
            const int k0 = (it + 1) * 32;
            float* Xn = Xb[(it + 1) & 1];
            float* Wn = Wb[(it + 1) & 1];
#pragma unroll
            for (int i = 0; i < 4; i++) {
                cp16(&Xn[xr * 36 + xk + i * 4], &X[(size_t)(m0 + xr) * 512 + k0 + xk + i * 4]);
                cp16(&Wn[wr * 136 + wc + i * 4], &W[(size_t)(k0 + wr) * 512 + n0 + wc + i * 4]);
            }
            CP_COMMIT();
        }
        const float* Xs = Xb[it & 1];
        const float* Ws = Wb[it & 1];
#pragma unroll
        for (int ks = 0; ks < 4; ks++) {
            const int kk = ks * 8;
            unsigned a[2][4];
#pragma unroll
            for (int mt = 0; mt < 2; mt++) {
                const int r0 = wm * 32 + mt * 16;
                a[mt][0] = f2tf(Xs[(r0 + g) * 36 + kk + t]);
                a[mt][1] = f2tf(Xs[(r0 + g + 8) * 36 + kk + t]);
                a[mt][2] = f2tf(Xs[(r0 + g) * 36 + kk + t + 4]);
                a[mt][3] = f2tf(Xs[(r0 + g + 8) * 36 + kk + t + 4]);
            }
#pragma unroll
            for (int nt = 0; nt < 8; nt++) {
                unsigned b[2];
                const int nn = wn * 64 + nt * 8 + g;
                b[0] = f2tf(Ws[(kk + t) * 136 + nn]);
                b[1] = f2tf(Ws[(kk + t + 4) * 136 + nn]);
                mma_tf32(acc[0][nt], a[0], b);
                mma_tf32(acc[1][nt], a[1], b);
            }
        }
        if (it < 15) {
            CP_WAIT0();
            __syncthreads();
        }
    }

    __half* Yh = (__half*)Y;
#pragma unroll
    for (int nt = 0; nt < 8; nt++) {
        const int colg = n0 + wn * 64 + nt * 8 + 2 * t;
        const float b0 = bias[colg], b1 = bias[colg + 1];
#pragma unroll
        for (int mt = 0; mt < 2; mt++) {
            const int rbase = m0 + wm * 32 + mt * 16;
#pragma unroll
            for (int half_ = 0; half_ < 2; half_++) {
                const int r = rbase + g + half_ * 8;
                float ox = acc[mt][nt][half_ * 2 + 0] + b0;
                float oy = acc[mt][nt][half_ * 2 + 1] + b1;
                if (MODE == 0) {
                    *(float2*)&Y[(size_t)r * 512 + colg] = make_float2(ox, oy);
                } else {
                    const int b = r >> 12, s = r & 4095;
                    const int h = colg >> 6, din = colg & 63;
                    *(__half2*)&Yh[(((size_t)(b * 8 + h)) * SS_ + s) * DEP + din] =
                        __floats2half2_rn(ox, oy);
                }
            }
        }
    }
}

// ---------------------------------------------------------------------------
// Rowsum prepass: replay GEMM1 (Q K^T, exp, causal) and write g_inv only.
// smem halves: Qs[128*72]=9216, Kst[3][64*72]=13824  => 23040 h = 46080 B.
// ---------------------------------------------------------------------------
__global__ void __launch_bounds__(256)
rowsum_kernel() {
    extern __shared__ __half smh[];
    __half* Qs = smh;

    const int tid = threadIdx.x;
    const int lane = tid & 31, w = tid >> 5;
    const int g = lane >> 2, t = lane & 3;
    const int rt = 31 - blockIdx.x;
    const int bh = blockIdx.y;
    const int row0 = rt * 128;

    const __half* __restrict__ Qh = g_qh + (size_t)bh * SS_ * DEP;
    const __half* __restrict__ Kh = g_kh + (size_t)bh * SS_ * DEP;

    const unsigned sbase = (unsigned)__cvta_generic_to_shared(smh);
    const unsigned kbase = sbase + 9216 * 2;

    const unsigned offA = (((lane & 15) * 72 + (lane >> 4) * 8) * 2);
    const unsigned offK = ((((lane >> 4) * 8 + (lane & 7)) * 72 + ((lane >> 3) & 1) * 8) * 2);
    const unsigned qpA = sbase + (w * 16 * 72) * 2 + offA;

    const int kvr = tid >> 2;
    const int c4 = tid & 3;

    // Prologue group 0: Q + K0
    {
        const int qr = tid >> 1;
        const int qo = (tid & 1) * 32;
#pragma unroll
        for (int i = 0; i < 4; i++)
            cp16(&Qs[qr * 72 + qo + i * 8], &Qh[(size_t)(row0 + qr) * DEP + qo + i * 8]);
    }
    __half* K0 = smh + 9216;
#pragma unroll
    for (int i = 0; i < 2; i++) {
        const int ho = 8 * c4 + 32 * i;
        cp16(&K0[kvr * 72 + ho], &Kh[(size_t)kvr * DEP + ho]);
    }
    CP_COMMIT();
    {
        __half* K1 = smh + 9216 + 4608;
#pragma unroll
        for (int i = 0; i < 2; i++) {
            const int ho = 8 * c4 + 32 * i;
            cp16(&K1[kvr * 72 + ho], &Kh[(size_t)(64 + kvr) * DEP + ho]);
        }
        CP_COMMIT();
    }
    CP_WAIT1();
    __syncthreads();

    unsigned qa[4][4];
#pragma unroll
    for (int ks = 0; ks < 4; ks++) ldsm4(qa[ks], qpA + ks * 32);

    float rs0 = 0.f, rs1 = 0.f;
    const int gi0 = row0 + w * 16 + g;
    const int gi1 = gi0 + 8;
    const int ctmax = 2 * rt + 1;
    const float C = 0.18033688f;  // 0.125 * log2(e)

    for (int ct = 0; ct <= ctmax; ct++) {
        if (ct + 2 <= ctmax) {
            const int st = (ct + 2) % 3;
            __half* Kn = smh + 9216 + st * 4608;
            const size_t gr = (size_t)((ct + 2) * 64 + kvr) * DEP;
#pragma unroll
            for (int i = 0; i < 2; i++) {
                const int ho = 8 * c4 + 32 * i;
                cp16(&Kn[kvr * 72 + ho], &Kh[gr + ho]);
            }
            CP_COMMIT();
        }

        const unsigned Kbp = kbase + (ct % 3) * 4608 * 2;

        float s[8][4];
#pragma unroll
        for (int nt = 0; nt < 8; nt++)
#pragma unroll
            for (int c = 0; c < 4; c++) s[nt][c] = 0.f;
#pragma unroll
        for (int ks = 0; ks < 4; ks++) {
#pragma unroll
            for (int ntp = 0; ntp < 4; ntp++) {
                unsigned bk[4];
                ldsm4(bk, Kbp + ntp * 2304 + ks * 32 + offK);
                mma_f16(s[2 * ntp],     qa[ks], bk);
                mma_f16(s[2 * ntp + 1], qa[ks], bk + 2);
            }
        }

#pragma unroll
        for (int nt = 0; nt < 8; nt++) {
            const int cj = ct * 64 + nt * 8 + 2 * t;
            rs0 += (cj     <= gi0) ? ex2(s[nt][0] * C) : 0.f;
            rs0 += (cj + 1 <= gi0) ? ex2(s[nt][1] * C) : 0.f;
            rs1 += (cj     <= gi1) ? ex2(s[nt][2] * C) : 0.f;
            rs1 += (cj + 1 <= gi1) ? ex2(s[nt][3] * C) : 0.f;
        }

        if (ct < ctmax) {
            if (ct + 2 <= ctmax) { CP_WAIT1(); } else { CP_WAIT0(); }
            __syncthreads();
        }
    }

    rs0 += __shfl_xor_sync(0xffffffffu, rs0, 1);
    rs0 += __shfl_xor_sync(0xffffffffu, rs0, 2);
    rs1 += __shfl_xor_sync(0xffffffffu, rs1, 1);
    rs1 += __shfl_xor_sync(0xffffffffu, rs1, 2);
    if (t == 0) {
        g_inv[(size_t)bh * SS_ + gi0] = 1.f / rs0;
        g_inv[(size_t)bh * SS_ + gi1] = 1.f / rs1;
    }
}

// ---------------------------------------------------------------------------
// Causal flash attention, fp16 m16n8k16 MMA, ldmatrix fragments,
// 3-stage cp.async K/V pipeline. Writes NORMALIZED P (inv from prepass),
// normalized ctx, and zero-fills the upper triangle in its tail.
// smem halves: Qs[128*72]=9216 (reused as Ps), Kst[3], Vst[3] => 73728 B.
// ---------------------------------------------------------------------------
__global__ void __launch_bounds__(256, 2)
attn_kernel(float* __restrict__ attn_out, int write_attn) {
    extern __shared__ __half smh[];
    __half* Qs = smh;

    const int tid = threadIdx.x;
    const int lane = tid & 31, w = tid >> 5;
    const int g = lane >> 2, t = lane & 3;
    const int rt = 31 - blockIdx.x;
    const int bh = blockIdx.y;
    const int row0 = rt * 128;

    const __half* __restrict__ Qh = g_qh + (size_t)bh * SS_ * DEP;
    const __half* __restrict__ Kh = g_kh + (size_t)bh * SS_ * DEP;
    const __half* __restrict__ Vh = g_vh + (size_t)bh * SS_ * DEP;

    const unsigned sbase = (unsigned)__cvta_generic_to_shared(smh);
    const unsigned kbase = sbase + 9216 * 2;
    const unsigned vbase = sbase + 23040 * 2;

    const unsigned offA = (((lane & 15) * 72 + (lane >> 4) * 8) * 2);
    const unsigned offK = ((((lane >> 4) * 8 + (lane & 7)) * 72 + ((lane >> 3) & 1) * 8) * 2);
    const unsigned qpA = sbase + (w * 16 * 72) * 2 + offA;

    const int kvr = tid >> 2;
    const int c4 = tid & 3;

    const int gi0 = row0 + w * 16 + g;
    const int gi1 = gi0 + 8;

    // inv from prepass (LDG overlaps prologue)
    const float inv0 = g_inv[(size_t)bh * SS_ + gi0];
    const float inv1 = g_inv[(size_t)bh * SS_ + gi1];

    // Prologue group 0: Q + K0 + V0
    {
        const int qr = tid >> 1;
        const int qo = (tid & 1) * 32;
#pragma unroll
        for (int i = 0; i < 4; i++)
            cp16(&Qs[qr * 72 + qo + i * 8], &Qh[(size_t)(row0 + qr) * DEP + qo + i * 8]);
    }
    __half* K0 = smh + 9216;
    __half* V0 = smh + 23040;
#pragma unroll
    for (int i = 0; i < 2; i++) {
        const int ho = 8 * c4 + 32 * i;
        cp16(&K0[kvr * 72 + ho], &Kh[(size_t)kvr * DEP + ho]);
        cp16(&V0[kvr * 72 + ho], &Vh[(size_t)kvr * DEP + ho]);
    }
    CP_COMMIT();
    {
        __half* K1 = smh + 9216 + 4608;
        __half* V1 = smh + 23040 + 4608;
#pragma unroll
        for (int i = 0; i < 2; i++) {
            const int ho = 8 * c4 + 32 * i;
            cp16(&K1[kvr * 72 + ho], &Kh[(size_t)(64 + kvr) * DEP + ho]);
            cp16(&V1[kvr * 72 + ho], &Vh[(size_t)(64 + kvr) * DEP + ho]);
        }
        CP_COMMIT();
    }
    CP_WAIT1();
    __syncthreads();

    unsigned qa[4][4];
#pragma unroll
    for (int ks = 0; ks < 4; ks++) ldsm4(qa[ks], qpA + ks * 32);

    float ctx[8][4];
#pragma unroll
    for (int nt = 0; nt < 8; nt++)
#pragma unroll
        for (int c = 0; c < 4; c++) ctx[nt][c] = 0.f;

    const int ctmax = 2 * rt + 1;
    const float C = 0.18033688f;  // 0.125 * log2(e)

    for (int ct = 0; ct <= ctmax; ct++) {
        if (ct + 2 <= ctmax) {
            const int st = (ct + 2) % 3;
            __half* Kn = smh + 9216 + st * 4608;
            __half* Vn = smh + 23040 + st * 4608;
            const size_t gr = (size_t)((ct + 2) * 64 + kvr) * DEP;
#pragma unroll
            for (int i = 0; i < 2; i++) {
                const int ho = 8 * c4 + 32 * i;
                cp16(&Kn[kvr * 72 + ho], &Kh[gr + ho]);
                cp16(&Vn[kvr * 72 + ho], &Vh[gr + ho]);
            }
            CP_COMMIT();
        }

        const int st = ct % 3;
        const unsigned Kbp = kbase + st * 4608 * 2;
        const unsigned Vbp = vbase + st * 4608 * 2;

        // GEMM1: S = Q K^T
        float s[8][4];
#pragma unroll
        for (int nt = 0; nt < 8; nt++)
#pragma unroll
            for (int c = 0; c < 4; c++) s[nt][c] = 0.f;
#pragma unroll
        for (int ks = 0; ks < 4; ks++) {
#pragma unroll
            for (int ntp = 0; ntp < 4; ntp++) {
                unsigned bk[4];
                ldsm4(bk, Kbp + ntp * 2304 + ks * 32 + offK);
                mma_f16(s[2 * ntp],     qa[ks], bk);
                mma_f16(s[2 * ntp + 1], qa[ks], bk + 2);
            }
        }

        // exp * inv (normalized); store fp32; stage fp16 (normalized)
#pragma unroll
        for (int nt = 0; nt < 8; nt++) {
            const int cj = ct * 64 + nt * 8 + 2 * t;
            float e00 = (cj     <= gi0) ? ex2(s[nt][0] * C) * inv0 : 0.f;
            float e01 = (cj + 1 <= gi0) ? ex2(s[nt][1] * C) * inv0 : 0.f;
            float e10 = (cj     <= gi1) ? ex2(s[nt][2] * C) * inv1 : 0.f;
            float e11 = (cj + 1 <= gi1) ? ex2(s[nt][3] * C) * inv1 : 0.f;
            if (write_attn) {
                __stcs((float2*)&attn_out[((size_t)bh * SS_ + gi0) * SS_ + cj],
                       make_float2(e00, e01));
                __stcs((float2*)&attn_out[((size_t)bh * SS_ + gi1) * SS_ + cj],
                       make_float2(e10, e11));
            }
            *(__half2*)&Qs[(w * 16 + g) * 72 + nt * 8 + 2 * t]     = __floats2half2_rn(e00, e01);
            *(__half2*)&Qs[(w * 16 + g + 8) * 72 + nt * 8 + 2 * t] = __floats2half2_rn(e10, e11);
        }
        __syncwarp();

        // GEMM2: ctx += P V (normalized P)
#pragma unroll
        for (int ks = 0; ks < 4; ks++) {
            unsigned pa[4];
            ldsm4(pa, qpA + ks * 32);
#pragma unroll
            for (int ntp = 0; ntp < 4; ntp++) {
                unsigned bv[4];
                ldsm4t(bv, Vbp + ks * 2304 + ntp * 32 + offA);
                mma_f16(ctx[2 * ntp],     pa, bv);
                mma_f16(ctx[2 * ntp + 1], pa, bv + 2);
            }
        }

        if (ct < ctmax) {
            if (ct + 2 <= ctmax) { CP_WAIT1(); } else { CP_WAIT0(); }
            __syncthreads();
        }
    }

    // Store ctx (already normalized)
    const int b = bh >> 3, h = bh & 7;
#pragma unroll
    for (int nt = 0; nt < 8; nt++) {
        const int d = nt * 8 + 2 * t;
        *(float2*)&g_ctx[((size_t)(b * SS_ + gi0)) * DD + h * 64 + d] =
            make_float2(ctx[nt][0], ctx[nt][1]);
        *(float2*)&g_ctx[((size_t)(b * SS_ + gi1)) * DD + h * 64 + d] =
            make_float2(ctx[nt][2], ctx[nt][3]);
    }

    // Zero-fill the upper triangle for this block's rows: cols >= 128*(rt+1)
    if (write_attn) {
        const int c0 = (rt + 1) * 128;
        const float4 z4 = make_float4(0.f, 0.f, 0.f, 0.f);
#pragma unroll 1
        for (int rr = 0; rr < 16; rr++) {
            float* rowp = attn_out + ((size_t)bh * SS_ + row0 + w * 16 + rr) * SS_;
            for (int c = c0 + lane * 4; c < SS_; c += 128)
                __stcs((float4*)(rowp + c), z4);
        }
    }
}

// ---------------------------------------------------------------------------
extern "C" void kernel_launch(void* const* d_in, const int* in_sizes, int n_in,
                              void* d_out, int out_size) {
    const float* q  = (const float*)d_in[2];
    const float* k  = (const float*)d_in[0];
    const float* v  = (const float*)d_in[1];
    const float* Wq = (const float*)d_in[4];
    const float* bq = (const float*)d_in[5];
    const float* Wk = (const float*)d_in[6];
    const float* bk = (const float*)d_in[7];
    const float* Wv = (const float*)d_in[8];
    const float* bv = (const float*)d_in[9];
    const float* Wo = (const float*)d_in[10];
    const float* bo = (const float*)d_in[11];

    float* out = (float*)d_out;
    const size_t BSD = (size_t)BB * SS_ * DD;
    const size_t ATT = (size_t)BH * SS_ * SS_;

    float* out_main = nullptr;
    float* attn_out = nullptr;
    if ((size_t)out_size >= BSD + ATT) {
        out_main = out;
        attn_out = out + BSD;
    } else if ((size_t)out_size >= ATT) {
        attn_out = out;
    } else {
        out_main = out;
    }

    void *pq, *pk, *pv, *pctx;
    cudaGetSymbolAddress(&pq, g_qh);
    cudaGetSymbolAddress(&pk, g_kh);
    cudaGetSymbolAddress(&pv, g_vh);
    cudaGetSymbolAddress(&pctx, g_ctx);

    cudaFuncSetAttribute(attn_kernel,
                         cudaFuncAttributeMaxDynamicSharedMemorySize, 73728);
    cudaFuncSetAttribute(rowsum_kernel,
                         cudaFuncAttributeMaxDynamicSharedMemorySize, 46080);
    cudaFuncSetAttribute(gemm512_mma<0>,
                         cudaFuncAttributeMaxDynamicSharedMemorySize, 71680);
    cudaFuncSetAttribute(gemm512_mma<1>,
                         cudaFuncAttributeMaxDynamicSharedMemorySize, 71680);

    dim3 ggrid(4, 64);
    gemm512_mma<1><<<ggrid, 256, 71680>>>(q, Wq, bq, (float*)pq);
    gemm512_mma<1><<<ggrid, 256, 71680>>>(k, Wk, bk, (float*)pk);
    gemm512_mma<1><<<ggrid, 256, 71680>>>(v, Wv, bv, (float*)pv);

    rowsum_kernel<<<dim3(32, BH), 256, 46080>>>();

    attn_kernel<<<dim3(32, BH), 256, 73728>>>(attn_out, attn_out != nullptr);

    if (out_main) {
        gemm512_mma<0><<<ggrid, 256, 71680>>>((const float*)pctx, Wo, bo, out_main);
    }
}

// round 13
// speedup vs baseline: 2.1666x; 1.2703x over previous
#include <cuda_runtime.h>
#include <cuda_fp16.h>
#include <math.h>

// Problem constants
#define BB   2
#define SS_  4096
#define DD   512
#define HH   8
#define DEP  64
#define BH   16
#define MM   8192

// fp16 copies of inputs/weights (f32to16 pass)
__device__ __half g_xq[MM * DD];
__device__ __half g_xk[MM * DD];
__device__ __half g_xv[MM * DD];
__device__ __half g_wq[DD * DD];
__device__ __half g_wk[DD * DD];
__device__ __half g_wv[DD * DD];
__device__ __half g_wo[DD * DD];
// Q/K/V head-split [bh][s][d] fp16, natural layout; ctx fp16 row-major.
__device__ __half g_qh[BH * SS_ * DEP];
__device__ __half g_kh[BH * SS_ * DEP];
__device__ __half g_vh[BH * SS_ * DEP];
__device__ __half g_ctxh[MM * DD];
__device__ float  g_inv[BH * SS_];

__device__ __forceinline__ float ex2(float x) {
    float y;
    asm("ex2.approx.ftz.f32 %0, %1;" : "=f"(y) : "f"(x));
    return y;
}

__device__ __forceinline__ void mma_f16(float* d, const unsigned* a, const unsigned* b) {
    asm volatile(
        "mma.sync.aligned.m16n8k16.row.col.f32.f16.f16.f32 "
        "{%0,%1,%2,%3}, {%4,%5,%6,%7}, {%8,%9}, {%0,%1,%2,%3};"
        : "+f"(d[0]), "+f"(d[1]), "+f"(d[2]), "+f"(d[3])
        : "r"(a[0]), "r"(a[1]), "r"(a[2]), "r"(a[3]), "r"(b[0]), "r"(b[1]));
}

__device__ __forceinline__ void ldsm4(unsigned* r, unsigned a) {
    asm volatile("ldmatrix.sync.aligned.m8n8.x4.shared.b16 {%0,%1,%2,%3}, [%4];"
                 : "=r"(r[0]), "=r"(r[1]), "=r"(r[2]), "=r"(r[3]) : "r"(a));
}
__device__ __forceinline__ void ldsm4t(unsigned* r, unsigned a) {
    asm volatile("ldmatrix.sync.aligned.m8n8.x4.trans.shared.b16 {%0,%1,%2,%3}, [%4];"
                 : "=r"(r[0]), "=r"(r[1]), "=r"(r[2]), "=r"(r[3]) : "r"(a));
}

__device__ __forceinline__ void cp16(void* smem_ptr, const void* gptr) {
    unsigned s = (unsigned)__cvta_generic_to_shared(smem_ptr);
    asm volatile("cp.async.cg.shared.global [%0], [%1], 16;" :: "r"(s), "l"(gptr));
}
#define CP_COMMIT() asm volatile("cp.async.commit_group;" ::: "memory")
#define CP_WAIT0()  asm volatile("cp.async.wait_group 0;" ::: "memory")
#define CP_WAIT1()  asm volatile("cp.async.wait_group 1;" ::: "memory")

// ---------------------------------------------------------------------------
// fp32 -> fp16 convert (vectorized)
// ---------------------------------------------------------------------------
__global__ void __launch_bounds__(256)
f32to16(const float* __restrict__ src, __half* __restrict__ dst) {
    const int i = blockIdx.x * 256 + threadIdx.x;   // float4 index
    float4 v = __ldcs(&((const float4*)src)[i]);
    __half2 a = __floats2half2_rn(v.x, v.y);
    __half2 b = __floats2half2_rn(v.z, v.w);
    uint2 u;
    u.x = *(unsigned*)&a; u.y = *(unsigned*)&b;
    *(uint2*)&dst[(size_t)i * 4] = u;
}

// ---------------------------------------------------------------------------
// fp16 GEMM: Y(8192x512) = Xh @ Wh + bias.  m16n8k16, ldmatrix, cp.async x2.
// BM=128, BN=128, BK=32. 8 warps (wm=w&3 over M, wn=w>>2 over N), warp 32x64.
// MODE 0: fp32 row-major out. MODE 1: head-split [bh][s][d] fp16 out.
// smem halves: Xs[2][128*40]=10240, Ws[2][32*136]=8704  => 18944 h = 37888 B
// ---------------------------------------------------------------------------
template <int MODE>
__global__ void __launch_bounds__(256, 2)
gemm_f16k(const __half* __restrict__ X, const __half* __restrict__ W,
          const float* __restrict__ bias, float* __restrict__ Y) {
    extern __shared__ __half hsm[];
    __half* Xb[2] = {hsm, hsm + 5120};              // [m][k] stride 40
    __half* Wb[2] = {hsm + 10240, hsm + 14592};     // [k][n] stride 136

    const int tid = threadIdx.x;
    const int lane = tid & 31, w = tid >> 5;
    const int g = lane >> 2, t = lane & 3;
    const int wm = w & 3, wn = w >> 2;
    const int m0 = blockIdx.y * 128, n0 = blockIdx.x * 128;

    const unsigned sbase = (unsigned)__cvta_generic_to_shared(hsm);
    // A-frag: rows = lane&15, k-half = lane>>4
    const unsigned offA = ((lane & 15) * 40 + (lane >> 4) * 8) * 2;
    // B-frag (trans on [k][n]): k rows = lane&15, n-group = lane>>4
    const unsigned offB = ((lane & 15) * 136 + (lane >> 4) * 8) * 2;

    float acc[2][8][4];
#pragma unroll
    for (int mt = 0; mt < 2; mt++)
#pragma unroll
        for (int nt = 0; nt < 8; nt++)
#pragma unroll
            for (int c = 0; c < 4; c++) acc[mt][nt][c] = 0.f;

    const int xr = tid >> 1;               // 0..127
    const int xc = (tid & 1) * 16;         // halves
    const int wr = tid >> 3;               // 0..31
    const int wc = (tid & 7) * 16;         // halves

#pragma unroll
    for (int i = 0; i < 2; i++) {
        cp16(&Xb[0][xr * 40 + xc + i * 8], &X[(size_t)(m0 + xr) * 512 + xc + i * 8]);
        cp16(&Wb[0][wr * 136 + wc + i * 8], &W[(size_t)wr * 512 + n0 + wc + i * 8]);
    }
    CP_COMMIT();
    CP_WAIT0();
    __syncthreads();

    for (int it = 0; it < 16; it++) {
        if (it < 15) {
            const int k0 = (it + 1) * 32;
            __half* Xn = Xb[(it + 1) & 1];
            __half* Wn = Wb[(it + 1) & 1];
#pragma unroll
            for (int i = 0; i < 2; i++) {
                cp16(&Xn[xr * 40 + xc + i * 8], &X[(size_t)(m0 + xr) * 512 + k0 + xc + i * 8]);
                cp16(&Wn[wr * 136 + wc + i * 8], &W[(size_t)(k0 + wr) * 512 + n0 + wc + i * 8]);
            }
            CP_COMMIT();
        }
        const unsigned Xp = sbase + (it & 1) * 5120 * 2;
        const unsigned Wp = sbase + 10240 * 2 + (it & 1) * 4352 * 2;

#pragma unroll
        for (int ks = 0; ks < 2; ks++) {
            unsigned a[2][4];
#pragma unroll
            for (int mt = 0; mt < 2; mt++)
                ldsm4(a[mt], Xp + ((wm * 32 + mt * 16) * 40 + ks * 16) * 2 + offA);
#pragma unroll
            for (int ntp = 0; ntp < 4; ntp++) {
                unsigned bv[4];
                ldsm4t(bv, Wp + (ks * 16 * 136 + wn * 64 + ntp * 16) * 2 + offB);
#pragma unroll
                for (int mt = 0; mt < 2; mt++) {
                    mma_f16(acc[mt][2 * ntp],     a[mt], bv);
                    mma_f16(acc[mt][2 * ntp + 1], a[mt], bv + 2);
                }
            }
        }
        if (it < 15) {
            CP_WAIT0();
            __syncthreads();
        }
    }

    __half* Yh = (__half*)Y;
#pragma unroll
    for (int nt = 0; nt < 8; nt++) {
        const int colg = n0 + wn * 64 + nt * 8 + 2 * t;
        const float b0 = bias[colg], b1 = bias[colg + 1];
#pragma unroll
        for (int mt = 0; mt < 2; mt++) {
            const int rbase = m0 + wm * 32 + mt * 16;
#pragma unroll
            for (int half_ = 0; half_ < 2; half_++) {
                const int r = rbase + g + half_ * 8;
                float ox = acc[mt][nt][half_ * 2 + 0] + b0;
                float oy = acc[mt][nt][half_ * 2 + 1] + b1;
                if (MODE == 0) {
                    *(float2*)&Y[(size_t)r * 512 + colg] = make_float2(ox, oy);
                } else {
                    const int b = r >> 12, s = r & 4095;
                    const int h = colg >> 6, din = colg & 63;
                    *(__half2*)&Yh[(((size_t)(b * 8 + h)) * SS_ + s) * DEP + din] =
                        __floats2half2_rn(ox, oy);
                }
            }
        }
    }
}

// ---------------------------------------------------------------------------
// Rowsum prepass: replay GEMM1 (Q K^T, exp, causal) and write g_inv only.
// smem halves: Qs[128*72]=9216, Kst[3][64*72]=13824  => 23040 h = 46080 B.
// ---------------------------------------------------------------------------
__global__ void __launch_bounds__(256)
rowsum_kernel() {
    extern __shared__ __half smh[];
    __half* Qs = smh;

    const int tid = threadIdx.x;
    const int lane = tid & 31, w = tid >> 5;
    const int g = lane >> 2, t = lane & 3;
    const int rt = 31 - blockIdx.x;
    const int bh = blockIdx.y;
    const int row0 = rt * 128;

    const __half* __restrict__ Qh = g_qh + (size_t)bh * SS_ * DEP;
    const __half* __restrict__ Kh = g_kh + (size_t)bh * SS_ * DEP;

    const unsigned sbase = (unsigned)__cvta_generic_to_shared(smh);
    const unsigned kbase = sbase + 9216 * 2;

    const unsigned offA = (((lane & 15) * 72 + (lane >> 4) * 8) * 2);
    const unsigned offK = ((((lane >> 4) * 8 + (lane & 7)) * 72 + ((lane >> 3) & 1) * 8) * 2);
    const unsigned qpA = sbase + (w * 16 * 72) * 2 + offA;

    const int kvr = tid >> 2;
    const int c4 = tid & 3;

    {
        const int qr = tid >> 1;
        const int qo = (tid & 1) * 32;
#pragma unroll
        for (int i = 0; i < 4; i++)
            cp16(&Qs[qr * 72 + qo + i * 8], &Qh[(size_t)(row0 + qr) * DEP + qo + i * 8]);
    }
    __half* K0 = smh + 9216;
#pragma unroll
    for (int i = 0; i < 2; i++) {
        const int ho = 8 * c4 + 32 * i;
        cp16(&K0[kvr * 72 + ho], &Kh[(size_t)kvr * DEP + ho]);
    }
    CP_COMMIT();
    {
        __half* K1 = smh + 9216 + 4608;
#pragma unroll
        for (int i = 0; i < 2; i++) {
            const int ho = 8 * c4 + 32 * i;
            cp16(&K1[kvr * 72 + ho], &Kh[(size_t)(64 + kvr) * DEP + ho]);
        }
        CP_COMMIT();
    }
    CP_WAIT1();
    __syncthreads();

    unsigned qa[4][4];
#pragma unroll
    for (int ks = 0; ks < 4; ks++) ldsm4(qa[ks], qpA + ks * 32);

    float rs0 = 0.f, rs1 = 0.f;
    const int gi0 = row0 + w * 16 + g;
    const int gi1 = gi0 + 8;
    const int ctmax = 2 * rt + 1;
    const float C = 0.18033688f;  // 0.125 * log2(e)

    for (int ct = 0; ct <= ctmax; ct++) {
        if (ct + 2 <= ctmax) {
            const int st = (ct + 2) % 3;
            __half* Kn = smh + 9216 + st * 4608;
            const size_t gr = (size_t)((ct + 2) * 64 + kvr) * DEP;
#pragma unroll
            for (int i = 0; i < 2; i++) {
                const int ho = 8 * c4 + 32 * i;
                cp16(&Kn[kvr * 72 + ho], &Kh[gr + ho]);
            }
            CP_COMMIT();
        }

        const unsigned Kbp = kbase + (ct % 3) * 4608 * 2;

        float s[8][4];
#pragma unroll
        for (int nt = 0; nt < 8; nt++)
#pragma unroll
            for (int c = 0; c < 4; c++) s[nt][c] = 0.f;
#pragma unroll
        for (int ks = 0; ks < 4; ks++) {
#pragma unroll
            for (int ntp = 0; ntp < 4; ntp++) {
                unsigned bk[4];
                ldsm4(bk, Kbp + ntp * 2304 + ks * 32 + offK);
                mma_f16(s[2 * ntp],     qa[ks], bk);
                mma_f16(s[2 * ntp + 1], qa[ks], bk + 2);
            }
        }

#pragma unroll
        for (int nt = 0; nt < 8; nt++) {
            const int cj = ct * 64 + nt * 8 + 2 * t;
            rs0 += (cj     <= gi0) ? ex2(s[nt][0] * C) : 0.f;
            rs0 += (cj + 1 <= gi0) ? ex2(s[nt][1] * C) : 0.f;
            rs1 += (cj     <= gi1) ? ex2(s[nt][2] * C) : 0.f;
            rs1 += (cj + 1 <= gi1) ? ex2(s[nt][3] * C) : 0.f;
        }

        if (ct < ctmax) {
            if (ct + 2 <= ctmax) { CP_WAIT1(); } else { CP_WAIT0(); }
            __syncthreads();
        }
    }

    rs0 += __shfl_xor_sync(0xffffffffu, rs0, 1);
    rs0 += __shfl_xor_sync(0xffffffffu, rs0, 2);
    rs1 += __shfl_xor_sync(0xffffffffu, rs1, 1);
    rs1 += __shfl_xor_sync(0xffffffffu, rs1, 2);
    if (t == 0) {
        g_inv[(size_t)bh * SS_ + gi0] = 1.f / rs0;
        g_inv[(size_t)bh * SS_ + gi1] = 1.f / rs1;
    }
}

// ---------------------------------------------------------------------------
// Causal flash attention. Writes NORMALIZED P, fp16 ctx, zero-fills upper tri.
// smem halves: Qs[128*72]=9216 (reused as Ps), Kst[3], Vst[3] => 73728 B.
// ---------------------------------------------------------------------------
__global__ void __launch_bounds__(256, 2)
attn_kernel(float* __restrict__ attn_out, int write_attn) {
    extern __shared__ __half smh[];
    __half* Qs = smh;

    const int tid = threadIdx.x;
    const int lane = tid & 31, w = tid >> 5;
    const int g = lane >> 2, t = lane & 3;
    const int rt = 31 - blockIdx.x;
    const int bh = blockIdx.y;
    const int row0 = rt * 128;

    const __half* __restrict__ Qh = g_qh + (size_t)bh * SS_ * DEP;
    const __half* __restrict__ Kh = g_kh + (size_t)bh * SS_ * DEP;
    const __half* __restrict__ Vh = g_vh + (size_t)bh * SS_ * DEP;

    const unsigned sbase = (unsigned)__cvta_generic_to_shared(smh);
    const unsigned kbase = sbase + 9216 * 2;
    const unsigned vbase = sbase + 23040 * 2;

    const unsigned offA = (((lane & 15) * 72 + (lane >> 4) * 8) * 2);
    const unsigned offK = ((((lane >> 4) * 8 + (lane & 7)) * 72 + ((lane >> 3) & 1) * 8) * 2);
    const unsigned qpA = sbase + (w * 16 * 72) * 2 + offA;

    const int kvr = tid >> 2;
    const int c4 = tid & 3;

    const int gi0 = row0 + w * 16 + g;
    const int gi1 = gi0 + 8;

    const float inv0 = g_inv[(size_t)bh * SS_ + gi0];
    const float inv1 = g_inv[(size_t)bh * SS_ + gi1];

    {
        const int qr = tid >> 1;
        const int qo = (tid & 1) * 32;
#pragma unroll
        for (int i = 0; i < 4; i++)
            cp16(&Qs[qr * 72 + qo + i * 8], &Qh[(size_t)(row0 + qr) * DEP + qo + i * 8]);
    }
    __half* K0 = smh + 9216;
    __half* V0 = smh + 23040;
#pragma unroll
    for (int i = 0; i < 2; i++) {
        const int ho = 8 * c4 + 32 * i;
        cp16(&K0[kvr * 72 + ho], &Kh[(size_t)kvr * DEP + ho]);
        cp16(&V0[kvr * 72 + ho], &Vh[(size_t)kvr * DEP + ho]);
    }
    CP_COMMIT();
    {
        __half* K1 = smh + 9216 + 4608;
        __half* V1 = smh + 23040 + 4608;
#pragma unroll
        for (int i = 0; i < 2; i++) {
            const int ho = 8 * c4 + 32 * i;
            cp16(&K1[kvr * 72 + ho], &Kh[(size_t)(64 + kvr) * DEP + ho]);
            cp16(&V1[kvr * 72 + ho], &Vh[(size_t)(64 + kvr) * DEP + ho]);
        }
        CP_COMMIT();
    }
    CP_WAIT1();
    __syncthreads();

    unsigned qa[4][4];
#pragma unroll
    for (int ks = 0; ks < 4; ks++) ldsm4(qa[ks], qpA + ks * 32);

    float ctx[8][4];
#pragma unroll
    for (int nt = 0; nt < 8; nt++)
#pragma unroll
        for (int c = 0; c < 4; c++) ctx[nt][c] = 0.f;

    const int ctmax = 2 * rt + 1;
    const float C = 0.18033688f;

    for (int ct = 0; ct <= ctmax; ct++) {
        if (ct + 2 <= ctmax) {
            const int st = (ct + 2) % 3;
            __half* Kn = smh + 9216 + st * 4608;
            __half* Vn = smh + 23040 + st * 4608;
            const size_t gr = (size_t)((ct + 2) * 64 + kvr) * DEP;
#pragma unroll
            for (int i = 0; i < 2; i++) {
                const int ho = 8 * c4 + 32 * i;
                cp16(&Kn[kvr * 72 + ho], &Kh[gr + ho]);
                cp16(&Vn[kvr * 72 + ho], &Vh[gr + ho]);
            }
            CP_COMMIT();
        }

        const int st = ct % 3;
        const unsigned Kbp = kbase + st * 4608 * 2;
        const unsigned Vbp = vbase + st * 4608 * 2;

        // GEMM1: S = Q K^T
        float s[8][4];
#pragma unroll
        for (int nt = 0; nt < 8; nt++)
#pragma unroll
            for (int c = 0; c < 4; c++) s[nt][c] = 0.f;
#pragma unroll
        for (int ks = 0; ks < 4; ks++) {
#pragma unroll
            for (int ntp = 0; ntp < 4; ntp++) {
                unsigned bk[4];
                ldsm4(bk, Kbp + ntp * 2304 + ks * 32 + offK);
                mma_f16(s[2 * ntp],     qa[ks], bk);
                mma_f16(s[2 * ntp + 1], qa[ks], bk + 2);
            }
        }

        // exp * inv (normalized); store fp32; stage fp16 (normalized)
#pragma unroll
        for (int nt = 0; nt < 8; nt++) {
            const int cj = ct * 64 + nt * 8 + 2 * t;
            float e00 = (cj     <= gi0) ? ex2(s[nt][0] * C) * inv0 : 0.f;
            float e01 = (cj + 1 <= gi0) ? ex2(s[nt][1] * C) * inv0 : 0.f;
            float e10 = (cj     <= gi1) ? ex2(s[nt][2] * C) * inv1 : 0.f;
            float e11 = (cj + 1 <= gi1) ? ex2(s[nt][3] * C) * inv1 : 0.f;
            if (write_attn) {
                __stcs((float2*)&attn_out[((size_t)bh * SS_ + gi0) * SS_ + cj],
                       make_float2(e00, e01));
                __stcs((float2*)&attn_out[((size_t)bh * SS_ + gi1) * SS_ + cj],
                       make_float2(e10, e11));
            }
            *(__half2*)&Qs[(w * 16 + g) * 72 + nt * 8 + 2 * t]     = __floats2half2_rn(e00, e01);
            *(__half2*)&Qs[(w * 16 + g + 8) * 72 + nt * 8 + 2 * t] = __floats2half2_rn(e10, e11);
        }
        __syncwarp();

        // GEMM2: ctx += P V
#pragma unroll
        for (int ks = 0; ks < 4; ks++) {
            unsigned pa[4];
            ldsm4(pa, qpA + ks * 32);
#pragma unroll
            for (int ntp = 0; ntp < 4; ntp++) {
                unsigned bv[4];
                ldsm4t(bv, Vbp + ks * 2304 + ntp * 32 + offA);
                mma_f16(ctx[2 * ntp],     pa, bv);
                mma_f16(ctx[2 * ntp + 1], pa, bv + 2);
            }
        }

        if (ct < ctmax) {
            if (ct + 2 <= ctmax) { CP_WAIT1(); } else { CP_WAIT0(); }
            __syncthreads();
        }
    }

    // Store ctx as fp16 (normalized; fed to fp16 out-proj)
    const int b = bh >> 3, h = bh & 7;
#pragma unroll
    for (int nt = 0; nt < 8; nt++) {
        const int d = nt * 8 + 2 * t;
        *(__half2*)&g_ctxh[((size_t)(b * SS_ + gi0)) * DD + h * 64 + d] =
            __floats2half2_rn(ctx[nt][0], ctx[nt][1]);
        *(__half2*)&g_ctxh[((size_t)(b * SS_ + gi1)) * DD + h * 64 + d] =
            __floats2half2_rn(ctx[nt][2], ctx[nt][3]);
    }

    // Zero-fill the upper triangle for this block's rows
    if (write_attn) {
        const int c0 = (rt + 1) * 128;
        const float4 z4 = make_float4(0.f, 0.f, 0.f, 0.f);
#pragma unroll 1
        for (int rr = 0; rr < 16; rr++) {
            float* rowp = attn_out + ((size_t)bh * SS_ + row0 + w * 16 + rr) * SS_;
            for (int c = c0 + lane * 4; c < SS_; c += 128)
                __stcs((float4*)(rowp + c), z4);
        }
    }
}

// ---------------------------------------------------------------------------
extern "C" void kernel_launch(void* const* d_in, const int* in_sizes, int n_in,
                              void* d_out, int out_size) {
    const float* q  = (const float*)d_in[2];
    const float* k  = (const float*)d_in[0];
    const float* v  = (const float*)d_in[1];
    const float* Wq = (const float*)d_in[4];
    const float* bq = (const float*)d_in[5];
    const float* Wk = (const float*)d_in[6];
    const float* bk = (const float*)d_in[7];
    const float* Wv = (const float*)d_in[8];
    const float* bv = (const float*)d_in[9];
    const float* Wo = (const float*)d_in[10];
    const float* bo = (const float*)d_in[11];

    float* out = (float*)d_out;
    const size_t BSD = (size_t)BB * SS_ * DD;
    const size_t ATT = (size_t)BH * SS_ * SS_;

    float* out_main = nullptr;
    float* attn_out = nullptr;
    if ((size_t)out_size >= BSD + ATT) {
        out_main = out;
        attn_out = out + BSD;
    } else if ((size_t)out_size >= ATT) {
        attn_out = out;
    } else {
        out_main = out;
    }

    void *pxq, *pxk, *pxv, *pwq, *pwk, *pwv, *pwo;
    void *pq, *pk, *pv, *pctx;
    cudaGetSymbolAddress(&pxq, g_xq);
    cudaGetSymbolAddress(&pxk, g_xk);
    cudaGetSymbolAddress(&pxv, g_xv);
    cudaGetSymbolAddress(&pwq, g_wq);
    cudaGetSymbolAddress(&pwk, g_wk);
    cudaGetSymbolAddress(&pwv, g_wv);
    cudaGetSymbolAddress(&pwo, g_wo);
    cudaGetSymbolAddress(&pq, g_qh);
    cudaGetSymbolAddress(&pk, g_kh);
    cudaGetSymbolAddress(&pv, g_vh);
    cudaGetSymbolAddress(&pctx, g_ctxh);

    cudaFuncSetAttribute(attn_kernel,
                         cudaFuncAttributeMaxDynamicSharedMemorySize, 73728);
    cudaFuncSetAttribute(rowsum_kernel,
                         cudaFuncAttributeMaxDynamicSharedMemorySize, 46080);
    cudaFuncSetAttribute(gemm_f16k<0>,
                         cudaFuncAttributeMaxDynamicSharedMemorySize, 37888);
    cudaFuncSetAttribute(gemm_f16k<1>,
                         cudaFuncAttributeMaxDynamicSharedMemorySize, 37888);

    // fp32 -> fp16 conversions (activations: 1,048,576 float4; weights: 65,536)
    f32to16<<<4096, 256>>>(q,  (__half*)pxq);
    f32to16<<<4096, 256>>>(k,  (__half*)pxk);
    f32to16<<<4096, 256>>>(v,  (__half*)pxv);
    f32to16<<<256,  256>>>(Wq, (__half*)pwq);
    f32to16<<<256,  256>>>(Wk, (__half*)pwk);
    f32to16<<<256,  256>>>(Wv, (__half*)pwv);
    f32to16<<<256,  256>>>(Wo, (__half*)pwo);

    dim3 ggrid(4, 64);
    gemm_f16k<1><<<ggrid, 256, 37888>>>((const __half*)pxq, (const __half*)pwq, bq, (float*)pq);
    gemm_f16k<1><<<ggrid, 256, 37888>>>((const __half*)pxk, (const __half*)pwk, bk, (float*)pk);
    gemm_f16k<1><<<ggrid, 256, 37888>>>((const __half*)pxv, (const __half*)pwv, bv, (float*)pv);

    rowsum_kernel<<<dim3(32, BH), 256, 46080>>>();

    attn_kernel<<<dim3(32, BH), 256, 73728>>>(attn_out, attn_out != nullptr);

    if (out_main) {
        gemm_f16k<0><<<ggrid, 256, 37888>>>((const __half*)pctx, (const __half*)pwo, bo, out_main);
    }
}